// round 12
// baseline (speedup 1.0000x reference)
#include <cuda_runtime.h>
#include <cuda_fp16.h>
#include <cuda_bf16.h>
#include <cstdint>

// Problem constants
#define BB   4
#define NN   16384
#define CC   64
#define KK   16
#define OUTC 128
#define BN   65536   // BB*NN
#define GRID1 512    // persistent grids: 2 tiles per block, single wave
#define NTILE 1024

typedef unsigned long long ull;

// packed fp32x2 fma: (d.lo,d.hi) = (a.lo*b.lo+d.lo, a.hi*b.hi+d.hi)
#define FFMA2(acc, a, b) asm("fma.rn.f32x2 %0, %1, %2, %0;" : "+l"(acc) : "l"(a), "l"(b))

static __device__ __forceinline__ float ull_hsum(ull v) {
    float2 f = *reinterpret_cast<float2*>(&v);
    return f.x + f.y;
}

// ---------------- scratch (device globals; no allocation) ----------------
__device__ __half g_h[(size_t)BN * CC];              // h[j] (fp16, 8MB)
__device__ __half g_tmp[(size_t)BB * OUTC * NN];     // unnormalized out (fp16, 16.8MB)
__device__ float g_sum[OUTC];
__device__ float g_sqs[OUTC];

// ---------------- K1: transpose + GEMM(Wmlp, packed f32x2) + softmax + ⊙flat -> g_h (fp16)
// Persistent: 512 blocks x 2 tiles (64 points each). Weights loaded once per block.
__global__ void __launch_bounds__(256) k1_mlp_h(const float* __restrict__ feat,
                                               const float* __restrict__ Wm) {
    __shared__ __align__(16) float Ft[64 * 66];
    __shared__ __align__(16) float Ws[64 * 66];
    int t = threadIdx.x;

    // fused k0: zero BN accumulators (ordered before k23's atomics by stream order)
    if (blockIdx.x == 0 && t < OUTC) { g_sum[t] = 0.f; g_sqs[t] = 0.f; }

    // load W_mlp[d][c] -> Ws[d*66+c] once (ull copy, c contiguous)
    const ull* wm2 = (const ull*)Wm;
#pragma unroll
    for (int r = 0; r < 8; r++) {
        int e2 = r * 256 + t;
        int d = e2 >> 5, c2 = e2 & 31;
        *(ull*)&Ws[d * 66 + (c2 << 1)] = wm2[e2];
    }

    int i4 = (t >> 4) << 2;
    int j  = t & 15;

#pragma unroll 1
    for (int it = 0; it < 2; it++) {
        int tile = blockIdx.x + it * GRID1;
        int b    = tile >> 8;           // 256 tiles per batch (N/64)
        int n0   = (tile & 255) << 6;

        if (it) __syncthreads();        // protect Ft reuse across tiles

        const float* fb = feat + (size_t)b * CC * NN;
        // load feature tile feature[b, c, n0+i] (coalesced over i) into Ft[i][c]
#pragma unroll
        for (int r = 0; r < 16; r++) {
            int e = r * 256 + t;
            int c = e >> 6, i = e & 63;
            Ft[i * 66 + c] = fb[c * NN + n0 + i];
        }
        __syncthreads();

        // GEMM: thread (i,j): pts i4..i4+3, d = j + 16q; reduction over c packed in pairs
        ull acc[4][4];
#pragma unroll
        for (int r = 0; r < 4; r++)
#pragma unroll
            for (int q = 0; q < 4; q++) acc[r][q] = 0ull;

#pragma unroll 8
        for (int cp = 0; cp < 32; cp++) {
            int c = cp << 1;
            ull p0 = *(const ull*)&Ft[(i4 + 0) * 66 + c];
            ull p1 = *(const ull*)&Ft[(i4 + 1) * 66 + c];
            ull p2 = *(const ull*)&Ft[(i4 + 2) * 66 + c];
            ull p3 = *(const ull*)&Ft[(i4 + 3) * 66 + c];
#pragma unroll
            for (int q = 0; q < 4; q++) {
                ull w = *(const ull*)&Ws[(j + (q << 4)) * 66 + c];
                FFMA2(acc[0][q], p0, w);
                FFMA2(acc[1][q], p1, w);
                FFMA2(acc[2][q], p2, w);
                FFMA2(acc[3][q], p3, w);
            }
        }

        // softmax over d (scores ~N(0,1): no max-subtraction needed), then ⊙ flat -> fp16
        size_t pbase = ((size_t)b * NN + n0) * CC;
#pragma unroll
        for (int r = 0; r < 4; r++) {
            float e0 = __expf(ull_hsum(acc[r][0]));
            float e1 = __expf(ull_hsum(acc[r][1]));
            float e2 = __expf(ull_hsum(acc[r][2]));
            float e3 = __expf(ull_hsum(acc[r][3]));
            float sum = (e0 + e1) + (e2 + e3);
#pragma unroll
            for (int d = 8; d > 0; d >>= 1)
                sum += __shfl_xor_sync(0xffffffffu, sum, d);
            float rinv = __fdividef(1.0f, sum);
            int pt = i4 + r;
            __half* hrow = g_h + pbase + (size_t)pt * 64;
            const float* frow = &Ft[pt * 66];
            hrow[j +  0] = __float2half_rn(e0 * rinv * frow[j +  0]);
            hrow[j + 16] = __float2half_rn(e1 * rinv * frow[j + 16]);
            hrow[j + 32] = __float2half_rn(e2 * rinv * frow[j + 32]);
            hrow[j + 48] = __float2half_rn(e3 * rinv * frow[j + 48]);
        }
    }
}

// ---------------- K23: fused gather-pool + GEMM(Wconv packed f32x2)+bias + BN partials
//                  + fp16 store of unnormalized out.
// Persistent: 512 blocks x 2 tiles. Dynamic shared: Ps[64][66] + Ws[128][66].
__global__ void __launch_bounds__(256) k23_pool_conv(const int* __restrict__ nidx,
                              const float* __restrict__ Wc, const float* __restrict__ bc) {
    extern __shared__ __align__(16) float sh[];
    float* Ps = sh;                  // [pt][c] pitch 66
    float* Ws = sh + 64 * 66;        // [o][c] pitch 66; reused as staging [o][pt] pitch 66
    int t = threadIdx.x;
    int warp = t >> 5, lane = t & 31;
    int i4 = (t >> 4) << 2;
    int j  = t & 15;
    const ull* wc2 = (const ull*)Wc;

#pragma unroll 1
    for (int it = 0; it < 2; it++) {
        int tile = blockIdx.x + it * GRID1;
        int b    = tile >> 8;
        int n0   = (tile & 255) << 6;
        size_t prow0 = ((size_t)b * NN + n0);

        if (it) __syncthreads();   // protect Ws/Ss + Ps reuse across tiles

        // load W_conv[o][c] -> Ws[o*66+c] (ull copy; reloaded per tile since Ws doubles as staging)
#pragma unroll
        for (int r = 0; r < 16; r++) {
            int e2 = r * 256 + t;
            int o = e2 >> 5, c2 = e2 & 31;
            *(ull*)&Ws[o * 66 + (c2 << 1)] = wc2[e2];
        }

        // gather-pool: warp w handles points 8w..8w+7; pooled_p = sum_k h[idx[p,k]]
        int4 myi = __ldg((const int4*)(nidx + ((prow0 + warp * 8) << 4)) + lane);
#pragma unroll 1
        for (int pi = 0; pi < 8; pi++) {
            int pt = warp * 8 + pi;
            float2 a0 = {0.f, 0.f}, a1 = {0.f, 0.f};
            float2 a2 = {0.f, 0.f}, a3 = {0.f, 0.f};
#pragma unroll
            for (int k = 0; k < KK; k += 8) {
                int f = pi * 16 + k;
                int j0 = __shfl_sync(0xffffffffu, myi.x, (f + 0) >> 2);
                int j1 = __shfl_sync(0xffffffffu, myi.y, (f + 1) >> 2);
                int j2 = __shfl_sync(0xffffffffu, myi.z, (f + 2) >> 2);
                int j3 = __shfl_sync(0xffffffffu, myi.w, (f + 3) >> 2);
                int j4 = __shfl_sync(0xffffffffu, myi.x, (f + 4) >> 2);
                int j5 = __shfl_sync(0xffffffffu, myi.y, (f + 5) >> 2);
                int j6 = __shfl_sync(0xffffffffu, myi.z, (f + 6) >> 2);
                int j7 = __shfl_sync(0xffffffffu, myi.w, (f + 7) >> 2);
                __half2 v0 = __ldg((const __half2*)(g_h + ((size_t)j0 << 6)) + lane);
                __half2 v1 = __ldg((const __half2*)(g_h + ((size_t)j1 << 6)) + lane);
                __half2 v2 = __ldg((const __half2*)(g_h + ((size_t)j2 << 6)) + lane);
                __half2 v3 = __ldg((const __half2*)(g_h + ((size_t)j3 << 6)) + lane);
                __half2 v4 = __ldg((const __half2*)(g_h + ((size_t)j4 << 6)) + lane);
                __half2 v5 = __ldg((const __half2*)(g_h + ((size_t)j5 << 6)) + lane);
                __half2 v6 = __ldg((const __half2*)(g_h + ((size_t)j6 << 6)) + lane);
                __half2 v7 = __ldg((const __half2*)(g_h + ((size_t)j7 << 6)) + lane);
                float2 f0 = __half22float2(v0), f1 = __half22float2(v1);
                float2 f2 = __half22float2(v2), f3 = __half22float2(v3);
                float2 f4 = __half22float2(v4), f5 = __half22float2(v5);
                float2 f6 = __half22float2(v6), f7 = __half22float2(v7);
                a0.x += f0.x; a0.y += f0.y;  a1.x += f1.x; a1.y += f1.y;
                a2.x += f2.x; a2.y += f2.y;  a3.x += f3.x; a3.y += f3.y;
                a0.x += f4.x; a0.y += f4.y;  a1.x += f5.x; a1.y += f5.y;
                a2.x += f6.x; a2.y += f6.y;  a3.x += f7.x; a3.y += f7.y;
            }
            float2 o2;
            o2.x = (a0.x + a1.x) + (a2.x + a3.x);
            o2.y = (a0.y + a1.y) + (a2.y + a3.y);
            *(float2*)&Ps[pt * 66 + 2 * lane] = o2;   // c = 2*lane, 2*lane+1
        }
        __syncthreads();

        // GEMM: thread (i,j): pts i4..i4+3, o = j + 16q, q in 0..7; c packed in pairs
        ull acc[4][8];
#pragma unroll
        for (int r = 0; r < 4; r++)
#pragma unroll
            for (int q = 0; q < 8; q++) acc[r][q] = 0ull;

#pragma unroll 4
        for (int cp = 0; cp < 32; cp++) {
            int c = cp << 1;
            ull p0 = *(const ull*)&Ps[(i4 + 0) * 66 + c];
            ull p1 = *(const ull*)&Ps[(i4 + 1) * 66 + c];
            ull p2 = *(const ull*)&Ps[(i4 + 2) * 66 + c];
            ull p3 = *(const ull*)&Ps[(i4 + 3) * 66 + c];
#pragma unroll
            for (int q = 0; q < 8; q++) {
                ull w = *(const ull*)&Ws[(j + (q << 4)) * 66 + c];
                FFMA2(acc[0][q], p0, w);
                FFMA2(acc[1][q], p1, w);
                FFMA2(acc[2][q], p2, w);
                FFMA2(acc[3][q], p3, w);
            }
        }
        __syncthreads();
        // stage result into Ss[o][pt] (reuse Ws region, pitch 66)
        float* Ss = Ws;
#pragma unroll
        for (int q = 0; q < 8; q++) {
            int o = j + (q << 4);
            float bb = __ldg(&bc[o]);
#pragma unroll
            for (int r = 0; r < 4; r++)
                Ss[o * 66 + i4 + r] = ull_hsum(acc[r][q]) + bb;
        }
        __syncthreads();

        // per-block BN partials (threads 0..127: one output channel each)
        if (t < OUTC) {
            float s = 0.f, s2 = 0.f;
#pragma unroll 8
            for (int pt = 0; pt < 64; pt++) {
                float v = Ss[t * 66 + pt];
                s += v;
                s2 = fmaf(v, v, s2);
            }
            atomicAdd(&g_sum[t], s);
            atomicAdd(&g_sqs[t], s2);
        }

        // coalesced fp16 store of the unnormalized tile: g_tmp[b, o, n0+i] (half2 packed)
        size_t obase = (size_t)b * OUTC * NN + n0;    // even
#pragma unroll
        for (int r = 0; r < 16; r++) {
            int e  = r * 256 + t;       // 4096 half2 elements: o = e>>5, i2 = e&31
            int o  = e >> 5, i2 = e & 31;
            __half2 hv = __floats2half2_rn(Ss[o * 66 + 2 * i2], Ss[o * 66 + 2 * i2 + 1]);
            *((__half2*)(g_tmp + obase + (size_t)o * NN) + i2) = hv;
        }
    }
}

// ---------------- K5: finalize BN stats per-thread + normalize fp16 tmp -> fp32 out ----------
__global__ void k5_norm(const float* __restrict__ gamma, const float* __restrict__ beta,
                        float* __restrict__ out) {
    int gi = blockIdx.x * blockDim.x + threadIdx.x;   // 0 .. 2M-1 float4s
    int o  = (gi >> 12) & (OUTC - 1);                 // 4096 float4 per (b,o) row
    const float invn = 1.0f / (float)BN;
    float mean = __ldg(&g_sum[o]) * invn;
    float var  = __ldg(&g_sqs[o]) * invn - mean * mean;
    float inv  = rsqrtf(var + 1e-5f);
    float a    = __ldg(&gamma[o]) * inv;
    float s    = __ldg(&beta[o]) - mean * a;
    const __half2* tp = (const __half2*)g_tmp + 2 * gi;
    float2 lo = __half22float2(__ldg(tp + 0));
    float2 hi = __half22float2(__ldg(tp + 1));
    float4 v;
    v.x = fmaf(lo.x, a, s);
    v.y = fmaf(lo.y, a, s);
    v.z = fmaf(hi.x, a, s);
    v.w = fmaf(hi.y, a, s);
    ((float4*)out)[gi] = v;
}

// ---------------- launch ----------------
extern "C" void kernel_launch(void* const* d_in, const int* in_sizes, int n_in,
                              void* d_out, int out_size) {
    const float* feat  = (const float*)d_in[0];
    const int*   nidx  = (const int*)d_in[1];
    // d_in[2] = permatrix (unused by forward)
    const float* Wm    = (const float*)d_in[3];
    const float* Wc    = (const float*)d_in[4];
    const float* bc    = (const float*)d_in[5];
    const float* gamma = (const float*)d_in[6];
    const float* beta  = (const float*)d_in[7];
    float*       out   = (float*)d_out;

    const int smem_k23 = (64 * 66 + 128 * 66) * (int)sizeof(float);  // 50688 B
    cudaFuncSetAttribute(k23_pool_conv, cudaFuncAttributeMaxDynamicSharedMemorySize, smem_k23);

    k1_mlp_h<<<GRID1, 256>>>(feat, Wm);
    k23_pool_conv<<<GRID1, 256, smem_k23>>>(nidx, Wc, bc);
    k5_norm<<<(BB * OUTC * NN / 4) / 256, 256>>>(gamma, beta, out);
}

// round 13
// speedup vs baseline: 1.1985x; 1.1985x over previous
#include <cuda_runtime.h>
#include <cuda_fp16.h>
#include <cuda_bf16.h>
#include <cstdint>

// Problem constants
#define BB   4
#define NN   16384
#define CC   64
#define KK   16
#define OUTC 128
#define BN   65536   // BB*NN

typedef unsigned long long ull;

// packed fp32x2 fma: (d.lo,d.hi) = (a.lo*b.lo+d.lo, a.hi*b.hi+d.hi)
#define FFMA2(acc, a, b) asm("fma.rn.f32x2 %0, %1, %2, %0;" : "+l"(acc) : "l"(a), "l"(b))

static __device__ __forceinline__ float ull_hsum(ull v) {
    float2 f = *reinterpret_cast<float2*>(&v);
    return f.x + f.y;
}

// ---------------- scratch (device globals; no allocation) ----------------
__device__ __half g_h[(size_t)BN * CC];              // h[j] (fp16, 8MB)
__device__ __half g_tmp[(size_t)BB * OUTC * NN];     // unnormalized out (fp16, 16.8MB)
__device__ float g_sum[OUTC];
__device__ float g_sqs[OUTC];

// ---------------- K1: transpose + GEMM(Wmlp, packed f32x2) + softmax + ⊙flat -> g_h (fp16)
// grid 1024 blocks (64-point tiles), 256 threads.  (identical to the 70.1us version)
__global__ void __launch_bounds__(256) k1_mlp_h(const float* __restrict__ feat,
                                               const float* __restrict__ Wm) {
    __shared__ float Ft[64 * 66];
    __shared__ float Ws[64 * 66];
    int blk = blockIdx.x;
    int b   = blk >> 8;            // 256 tiles per batch (N/64)
    int n0  = (blk & 255) << 6;
    int t   = threadIdx.x;

    // fused k0: zero BN accumulators (ordered before k23's atomics by stream order)
    if (blk == 0 && t < OUTC) { g_sum[t] = 0.f; g_sqs[t] = 0.f; }

    const float* fb = feat + (size_t)b * CC * NN;
    // load feature tile feature[b, c, n0+i] (coalesced over i) into Ft[i][c]
#pragma unroll
    for (int r = 0; r < 16; r++) {
        int e = r * 256 + t;
        int c = e >> 6, i = e & 63;
        Ft[i * 66 + c] = fb[c * NN + n0 + i];
    }
    // load W_mlp[d][c] -> Ws[d*66+c] (c contiguous)
#pragma unroll
    for (int r = 0; r < 16; r++) {
        int e = r * 256 + t;
        int d = e >> 6, c = e & 63;
        Ws[d * 66 + c] = Wm[e];
    }
    __syncthreads();

    // GEMM: thread (i,j): pts i4..i4+3, d = j + 16q; reduction over c packed in pairs
    int i4 = (t >> 4) << 2;
    int j  = t & 15;
    ull acc[4][4];
#pragma unroll
    for (int r = 0; r < 4; r++)
#pragma unroll
        for (int q = 0; q < 4; q++) acc[r][q] = 0ull;

#pragma unroll 8
    for (int cp = 0; cp < 32; cp++) {
        int c = cp << 1;
        ull p0 = *(const ull*)&Ft[(i4 + 0) * 66 + c];
        ull p1 = *(const ull*)&Ft[(i4 + 1) * 66 + c];
        ull p2 = *(const ull*)&Ft[(i4 + 2) * 66 + c];
        ull p3 = *(const ull*)&Ft[(i4 + 3) * 66 + c];
#pragma unroll
        for (int q = 0; q < 4; q++) {
            ull w = *(const ull*)&Ws[(j + (q << 4)) * 66 + c];
            FFMA2(acc[0][q], p0, w);
            FFMA2(acc[1][q], p1, w);
            FFMA2(acc[2][q], p2, w);
            FFMA2(acc[3][q], p3, w);
        }
    }

    // softmax over d (scores ~N(0,1): no max-subtraction needed), then ⊙ flat -> fp16
    size_t pbase = ((size_t)b * NN + n0) * CC;
#pragma unroll
    for (int r = 0; r < 4; r++) {
        float e0 = __expf(ull_hsum(acc[r][0]));
        float e1 = __expf(ull_hsum(acc[r][1]));
        float e2 = __expf(ull_hsum(acc[r][2]));
        float e3 = __expf(ull_hsum(acc[r][3]));
        float sum = (e0 + e1) + (e2 + e3);
#pragma unroll
        for (int d = 8; d > 0; d >>= 1)
            sum += __shfl_xor_sync(0xffffffffu, sum, d);
        float rinv = __fdividef(1.0f, sum);
        int pt = i4 + r;
        __half* hrow = g_h + pbase + (size_t)pt * 64;
        const float* frow = &Ft[pt * 66];
        hrow[j +  0] = __float2half_rn(e0 * rinv * frow[j +  0]);
        hrow[j + 16] = __float2half_rn(e1 * rinv * frow[j + 16]);
        hrow[j + 32] = __float2half_rn(e2 * rinv * frow[j + 32]);
        hrow[j + 48] = __float2half_rn(e3 * rinv * frow[j + 48]);
    }
}

// ---------------- K23: fused gather-pool + split GEMM(Wconv)+bias + BN partials
//                  + fp16 store of unnormalized out.
// GEMM is split into two o-halves (q=0..3, q=4..7) to halve accumulator registers:
// target 3 blocks/SM (was 2) for fewer waves + better gather latency hiding.
// grid 1024 (64-point tiles) x 256 threads. Dynamic shared: Ps[64][66] + Ws[128][66].
__global__ void __launch_bounds__(256, 3) k23_pool_conv(const int* __restrict__ nidx,
                              const float* __restrict__ Wc, const float* __restrict__ bc) {
    extern __shared__ float sh[];
    float* Ps = sh;                  // [pt][c] pitch 66
    float* Ws = sh + 64 * 66;        // [o][c] pitch 66; halves reused as staging [o][pt]
    int blk = blockIdx.x;
    int b   = blk >> 8;
    int n0  = (blk & 255) << 6;
    int t   = threadIdx.x;
    int warp = t >> 5, lane = t & 31;

    // load W_conv[o][c] -> Ws[o*66+c] (no sync needed before gather writes to Ps)
#pragma unroll
    for (int r = 0; r < 32; r++) {
        int e = r * 256 + t;
        Ws[(e >> 6) * 66 + (e & 63)] = Wc[e];
    }

    // gather-pool: warp w handles points 8w..8w+7; pooled_p = sum_k h[idx[p,k]]
    size_t prow0 = ((size_t)b * NN + n0);
    int4 myi = __ldg((const int4*)(nidx + ((prow0 + warp * 8) << 4)) + lane);
#pragma unroll 1
    for (int pi = 0; pi < 8; pi++) {
        int pt = warp * 8 + pi;
        float2 a0 = {0.f, 0.f}, a1 = {0.f, 0.f};
        float2 a2 = {0.f, 0.f}, a3 = {0.f, 0.f};
#pragma unroll
        for (int k = 0; k < KK; k += 8) {
            int f = pi * 16 + k;
            int j0 = __shfl_sync(0xffffffffu, myi.x, (f + 0) >> 2);
            int j1 = __shfl_sync(0xffffffffu, myi.y, (f + 1) >> 2);
            int j2 = __shfl_sync(0xffffffffu, myi.z, (f + 2) >> 2);
            int j3 = __shfl_sync(0xffffffffu, myi.w, (f + 3) >> 2);
            int j4 = __shfl_sync(0xffffffffu, myi.x, (f + 4) >> 2);
            int j5 = __shfl_sync(0xffffffffu, myi.y, (f + 5) >> 2);
            int j6 = __shfl_sync(0xffffffffu, myi.z, (f + 6) >> 2);
            int j7 = __shfl_sync(0xffffffffu, myi.w, (f + 7) >> 2);
            __half2 v0 = __ldg((const __half2*)(g_h + ((size_t)j0 << 6)) + lane);
            __half2 v1 = __ldg((const __half2*)(g_h + ((size_t)j1 << 6)) + lane);
            __half2 v2 = __ldg((const __half2*)(g_h + ((size_t)j2 << 6)) + lane);
            __half2 v3 = __ldg((const __half2*)(g_h + ((size_t)j3 << 6)) + lane);
            __half2 v4 = __ldg((const __half2*)(g_h + ((size_t)j4 << 6)) + lane);
            __half2 v5 = __ldg((const __half2*)(g_h + ((size_t)j5 << 6)) + lane);
            __half2 v6 = __ldg((const __half2*)(g_h + ((size_t)j6 << 6)) + lane);
            __half2 v7 = __ldg((const __half2*)(g_h + ((size_t)j7 << 6)) + lane);
            float2 f0 = __half22float2(v0), f1 = __half22float2(v1);
            float2 f2 = __half22float2(v2), f3 = __half22float2(v3);
            float2 f4 = __half22float2(v4), f5 = __half22float2(v5);
            float2 f6 = __half22float2(v6), f7 = __half22float2(v7);
            a0.x += f0.x; a0.y += f0.y;  a1.x += f1.x; a1.y += f1.y;
            a2.x += f2.x; a2.y += f2.y;  a3.x += f3.x; a3.y += f3.y;
            a0.x += f4.x; a0.y += f4.y;  a1.x += f5.x; a1.y += f5.y;
            a2.x += f6.x; a2.y += f6.y;  a3.x += f7.x; a3.y += f7.y;
        }
        float2 o2;
        o2.x = (a0.x + a1.x) + (a2.x + a3.x);
        o2.y = (a0.y + a1.y) + (a2.y + a3.y);
        *(float2*)&Ps[pt * 66 + 2 * lane] = o2;   // c = 2*lane, 2*lane+1
    }
    __syncthreads();

    int i4 = (t >> 4) << 2;
    int j  = t & 15;
    float* Ss = Ws;   // staging [o][pt] pitch 66, same region as weights

    // ---- pass A: o = j + 16q, q in 0..3 (weight rows 0..63) ----
    {
        ull acc[4][4];
#pragma unroll
        for (int r = 0; r < 4; r++)
#pragma unroll
            for (int q = 0; q < 4; q++) acc[r][q] = 0ull;

#pragma unroll 8
        for (int cp = 0; cp < 32; cp++) {
            int c = cp << 1;
            ull p0 = *(const ull*)&Ps[(i4 + 0) * 66 + c];
            ull p1 = *(const ull*)&Ps[(i4 + 1) * 66 + c];
            ull p2 = *(const ull*)&Ps[(i4 + 2) * 66 + c];
            ull p3 = *(const ull*)&Ps[(i4 + 3) * 66 + c];
#pragma unroll
            for (int q = 0; q < 4; q++) {
                ull w = *(const ull*)&Ws[(j + (q << 4)) * 66 + c];
                FFMA2(acc[0][q], p0, w);
                FFMA2(acc[1][q], p1, w);
                FFMA2(acc[2][q], p2, w);
                FFMA2(acc[3][q], p3, w);
            }
        }
        __syncthreads();   // all pass-A weight reads done -> rows 0..63 reusable
#pragma unroll
        for (int q = 0; q < 4; q++) {
            int o = j + (q << 4);
            float bb = __ldg(&bc[o]);
#pragma unroll
            for (int r = 0; r < 4; r++)
                Ss[o * 66 + i4 + r] = ull_hsum(acc[r][q]) + bb;
        }
    }

    // ---- pass B: o = 64 + j + 16q, q in 0..3 (weight rows 64..127) ----
    {
        ull acc[4][4];
#pragma unroll
        for (int r = 0; r < 4; r++)
#pragma unroll
            for (int q = 0; q < 4; q++) acc[r][q] = 0ull;

#pragma unroll 8
        for (int cp = 0; cp < 32; cp++) {
            int c = cp << 1;
            ull p0 = *(const ull*)&Ps[(i4 + 0) * 66 + c];
            ull p1 = *(const ull*)&Ps[(i4 + 1) * 66 + c];
            ull p2 = *(const ull*)&Ps[(i4 + 2) * 66 + c];
            ull p3 = *(const ull*)&Ps[(i4 + 3) * 66 + c];
#pragma unroll
            for (int q = 0; q < 4; q++) {
                ull w = *(const ull*)&Ws[(64 + j + (q << 4)) * 66 + c];
                FFMA2(acc[0][q], p0, w);
                FFMA2(acc[1][q], p1, w);
                FFMA2(acc[2][q], p2, w);
                FFMA2(acc[3][q], p3, w);
            }
        }
        __syncthreads();   // all pass-B weight reads done -> rows 64..127 reusable
#pragma unroll
        for (int q = 0; q < 4; q++) {
            int o = 64 + j + (q << 4);
            float bb = __ldg(&bc[o]);
#pragma unroll
            for (int r = 0; r < 4; r++)
                Ss[o * 66 + i4 + r] = ull_hsum(acc[r][q]) + bb;
        }
    }
    __syncthreads();

    // per-block BN partials (threads 0..127: one output channel each)
    if (t < OUTC) {
        float s = 0.f, s2 = 0.f;
#pragma unroll 8
        for (int pt = 0; pt < 64; pt++) {
            float v = Ss[t * 66 + pt];
            s += v;
            s2 = fmaf(v, v, s2);
        }
        atomicAdd(&g_sum[t], s);
        atomicAdd(&g_sqs[t], s2);
    }

    // coalesced fp16 store of the unnormalized tile: g_tmp[b, o, n0+i] (half2 packed)
    size_t obase = (size_t)b * OUTC * NN + n0;    // even
#pragma unroll
    for (int r = 0; r < 16; r++) {
        int e  = r * 256 + t;       // 4096 half2 elements: o = e>>5, i2 = e&31
        int o  = e >> 5, i2 = e & 31;
        __half2 hv = __floats2half2_rn(Ss[o * 66 + 2 * i2], Ss[o * 66 + 2 * i2 + 1]);
        *((__half2*)(g_tmp + obase + (size_t)o * NN) + i2) = hv;
    }
}

// ---------------- K5: finalize BN stats per-thread + normalize fp16 tmp -> fp32 out ----------
__global__ void k5_norm(const float* __restrict__ gamma, const float* __restrict__ beta,
                        float* __restrict__ out) {
    int gi = blockIdx.x * blockDim.x + threadIdx.x;   // 0 .. 2M-1 float4s
    int o  = (gi >> 12) & (OUTC - 1);                 // 4096 float4 per (b,o) row
    const float invn = 1.0f / (float)BN;
    float mean = __ldg(&g_sum[o]) * invn;
    float var  = __ldg(&g_sqs[o]) * invn - mean * mean;
    float inv  = rsqrtf(var + 1e-5f);
    float a    = __ldg(&gamma[o]) * inv;
    float s    = __ldg(&beta[o]) - mean * a;
    const __half2* tp = (const __half2*)g_tmp + 2 * gi;
    float2 lo = __half22float2(__ldg(tp + 0));
    float2 hi = __half22float2(__ldg(tp + 1));
    float4 v;
    v.x = fmaf(lo.x, a, s);
    v.y = fmaf(lo.y, a, s);
    v.z = fmaf(hi.x, a, s);
    v.w = fmaf(hi.y, a, s);
    ((float4*)out)[gi] = v;
}

// ---------------- launch ----------------
extern "C" void kernel_launch(void* const* d_in, const int* in_sizes, int n_in,
                              void* d_out, int out_size) {
    const float* feat  = (const float*)d_in[0];
    const int*   nidx  = (const int*)d_in[1];
    // d_in[2] = permatrix (unused by forward)
    const float* Wm    = (const float*)d_in[3];
    const float* Wc    = (const float*)d_in[4];
    const float* bc    = (const float*)d_in[5];
    const float* gamma = (const float*)d_in[6];
    const float* beta  = (const float*)d_in[7];
    float*       out   = (float*)d_out;

    const int smem_k23 = (64 * 66 + 128 * 66) * (int)sizeof(float);  // 50688 B
    cudaFuncSetAttribute(k23_pool_conv, cudaFuncAttributeMaxDynamicSharedMemorySize, smem_k23);

    k1_mlp_h<<<BN / 64, 256>>>(feat, Wm);
    k23_pool_conv<<<BN / 64, 256, smem_k23>>>(nidx, Wc, bc);
    k5_norm<<<(BB * OUTC * NN / 4) / 256, 256>>>(gamma, beta, out);
}

// round 14
// speedup vs baseline: 1.6180x; 1.3500x over previous
#include <cuda_runtime.h>
#include <cuda_fp16.h>
#include <cuda_bf16.h>
#include <cstdint>

// Problem constants
#define BB   4
#define NN   16384
#define CC   64
#define KK   16
#define OUTC 128
#define BN   65536   // BB*NN

typedef unsigned long long ull;

// packed fp32x2 fma: (d.lo,d.hi) = (a.lo*b.lo+d.lo, a.hi*b.hi+d.hi)
#define FFMA2(acc, a, b) asm("fma.rn.f32x2 %0, %1, %2, %0;" : "+l"(acc) : "l"(a), "l"(b))

#define LDMX4(r0, r1, r2, r3, addr) \
    asm volatile("ldmatrix.sync.aligned.m8n8.x4.shared.b16 {%0,%1,%2,%3}, [%4];" \
        : "=r"(r0), "=r"(r1), "=r"(r2), "=r"(r3) : "r"(addr))

#define MMA16816(c0, c1, c2, c3, a0, a1, a2, a3, b0, b1) \
    asm volatile("mma.sync.aligned.m16n8k16.row.col.f32.f16.f16.f32 " \
        "{%0,%1,%2,%3}, {%4,%5,%6,%7}, {%8,%9}, {%0,%1,%2,%3};" \
        : "+f"(c0), "+f"(c1), "+f"(c2), "+f"(c3) \
        : "r"(a0), "r"(a1), "r"(a2), "r"(a3), "r"(b0), "r"(b1))

static __device__ __forceinline__ float ull_hsum(ull v) {
    float2 f = *reinterpret_cast<float2*>(&v);
    return f.x + f.y;
}

// ---------------- scratch (device globals; no allocation) ----------------
__device__ __half g_h[(size_t)BN * CC];              // h[j] (fp16, 8MB)
__device__ __half g_tmp[(size_t)BB * OUTC * NN];     // unnormalized out (fp16, 16.8MB)
__device__ float g_sum[OUTC];
__device__ float g_sqs[OUTC];

// ---------------- K1: transpose + GEMM(Wmlp, packed f32x2) + softmax + ⊙flat -> g_h (fp16)
// grid 1024 blocks (64-point tiles), 256 threads.  (identical to the 70.1us version)
__global__ void __launch_bounds__(256) k1_mlp_h(const float* __restrict__ feat,
                                               const float* __restrict__ Wm) {
    __shared__ float Ft[64 * 66];
    __shared__ float Ws[64 * 66];
    int blk = blockIdx.x;
    int b   = blk >> 8;            // 256 tiles per batch (N/64)
    int n0  = (blk & 255) << 6;
    int t   = threadIdx.x;

    // fused k0: zero BN accumulators (ordered before k23's atomics by stream order)
    if (blk == 0 && t < OUTC) { g_sum[t] = 0.f; g_sqs[t] = 0.f; }

    const float* fb = feat + (size_t)b * CC * NN;
    // load feature tile feature[b, c, n0+i] (coalesced over i) into Ft[i][c]
#pragma unroll
    for (int r = 0; r < 16; r++) {
        int e = r * 256 + t;
        int c = e >> 6, i = e & 63;
        Ft[i * 66 + c] = fb[c * NN + n0 + i];
    }
    // load W_mlp[d][c] -> Ws[d*66+c] (c contiguous)
#pragma unroll
    for (int r = 0; r < 16; r++) {
        int e = r * 256 + t;
        int d = e >> 6, c = e & 63;
        Ws[d * 66 + c] = Wm[e];
    }
    __syncthreads();

    // GEMM: thread (i,j): pts i4..i4+3, d = j + 16q; reduction over c packed in pairs
    int i4 = (t >> 4) << 2;
    int j  = t & 15;
    ull acc[4][4];
#pragma unroll
    for (int r = 0; r < 4; r++)
#pragma unroll
        for (int q = 0; q < 4; q++) acc[r][q] = 0ull;

#pragma unroll 8
    for (int cp = 0; cp < 32; cp++) {
        int c = cp << 1;
        ull p0 = *(const ull*)&Ft[(i4 + 0) * 66 + c];
        ull p1 = *(const ull*)&Ft[(i4 + 1) * 66 + c];
        ull p2 = *(const ull*)&Ft[(i4 + 2) * 66 + c];
        ull p3 = *(const ull*)&Ft[(i4 + 3) * 66 + c];
#pragma unroll
        for (int q = 0; q < 4; q++) {
            ull w = *(const ull*)&Ws[(j + (q << 4)) * 66 + c];
            FFMA2(acc[0][q], p0, w);
            FFMA2(acc[1][q], p1, w);
            FFMA2(acc[2][q], p2, w);
            FFMA2(acc[3][q], p3, w);
        }
    }

    // softmax over d (scores ~N(0,1): no max-subtraction needed), then ⊙ flat -> fp16
    size_t pbase = ((size_t)b * NN + n0) * CC;
#pragma unroll
    for (int r = 0; r < 4; r++) {
        float e0 = __expf(ull_hsum(acc[r][0]));
        float e1 = __expf(ull_hsum(acc[r][1]));
        float e2 = __expf(ull_hsum(acc[r][2]));
        float e3 = __expf(ull_hsum(acc[r][3]));
        float sum = (e0 + e1) + (e2 + e3);
#pragma unroll
        for (int d = 8; d > 0; d >>= 1)
            sum += __shfl_xor_sync(0xffffffffu, sum, d);
        float rinv = __fdividef(1.0f, sum);
        int pt = i4 + r;
        __half* hrow = g_h + pbase + (size_t)pt * 64;
        const float* frow = &Ft[pt * 66];
        hrow[j +  0] = __float2half_rn(e0 * rinv * frow[j +  0]);
        hrow[j + 16] = __float2half_rn(e1 * rinv * frow[j + 16]);
        hrow[j + 32] = __float2half_rn(e2 * rinv * frow[j + 32]);
        hrow[j + 48] = __float2half_rn(e3 * rinv * frow[j + 48]);
    }
}

// ---------------- K23: fused gather-pool + fp16 HMMA GEMM(Wconv)+bias + BN partials
//                  + fp16 store of unnormalized out.
// grid 1024 (64-point tiles) x 256 threads.
// smem union: Ps_h[64][72] fp16 (9216B) | Ws_h[128][72] fp16 (18432B),
// aliased after GEMM by Ss[128][66] fp32 (33792B = total dynamic smem).
#define PS_BYTES (64 * 72 * 2)
__global__ void __launch_bounds__(256) k23_pool_conv(const int* __restrict__ nidx,
                              const float* __restrict__ Wc, const float* __restrict__ bc) {
    extern __shared__ __align__(16) char shb[];
    __half* Ps_h = (__half*)shb;                 // [pt][c] pitch 72 halves
    __half* Ws_h = (__half*)(shb + PS_BYTES);    // [o][c] pitch 72 halves
    float*  Ss   = (float*)shb;                  // [o][pt] pitch 66, alias after GEMM

    int blk = blockIdx.x;
    int b   = blk >> 8;
    int n0  = (blk & 255) << 6;
    int t   = threadIdx.x;
    int warp = t >> 5, lane = t & 31;

    // load + convert W_conv[o][c] -> fp16 Ws_h (no sync needed before gather writes Ps_h)
    const float2* wc2 = (const float2*)Wc;
#pragma unroll
    for (int r = 0; r < 16; r++) {
        int e2 = r * 256 + t;            // 4096 float2
        int o = e2 >> 5, c2 = e2 & 31;
        float2 wv = __ldg(wc2 + e2);
        *(__half2*)&Ws_h[o * 72 + (c2 << 1)] = __floats2half2_rn(wv.x, wv.y);
    }

    // gather-pool: warp w handles points 8w..8w+7; pooled_p = sum_k h[idx[p,k]]
    size_t prow0 = ((size_t)b * NN + n0);
    int4 myi = __ldg((const int4*)(nidx + ((prow0 + warp * 8) << 4)) + lane);
#pragma unroll 1
    for (int pi = 0; pi < 8; pi++) {
        int pt = warp * 8 + pi;
        float2 a0 = {0.f, 0.f}, a1 = {0.f, 0.f};
        float2 a2 = {0.f, 0.f}, a3 = {0.f, 0.f};
#pragma unroll
        for (int k = 0; k < KK; k += 8) {
            int f = pi * 16 + k;
            int j0 = __shfl_sync(0xffffffffu, myi.x, (f + 0) >> 2);
            int j1 = __shfl_sync(0xffffffffu, myi.y, (f + 1) >> 2);
            int j2 = __shfl_sync(0xffffffffu, myi.z, (f + 2) >> 2);
            int j3 = __shfl_sync(0xffffffffu, myi.w, (f + 3) >> 2);
            int j4 = __shfl_sync(0xffffffffu, myi.x, (f + 4) >> 2);
            int j5 = __shfl_sync(0xffffffffu, myi.y, (f + 5) >> 2);
            int j6 = __shfl_sync(0xffffffffu, myi.z, (f + 6) >> 2);
            int j7 = __shfl_sync(0xffffffffu, myi.w, (f + 7) >> 2);
            __half2 v0 = __ldg((const __half2*)(g_h + ((size_t)j0 << 6)) + lane);
            __half2 v1 = __ldg((const __half2*)(g_h + ((size_t)j1 << 6)) + lane);
            __half2 v2 = __ldg((const __half2*)(g_h + ((size_t)j2 << 6)) + lane);
            __half2 v3 = __ldg((const __half2*)(g_h + ((size_t)j3 << 6)) + lane);
            __half2 v4 = __ldg((const __half2*)(g_h + ((size_t)j4 << 6)) + lane);
            __half2 v5 = __ldg((const __half2*)(g_h + ((size_t)j5 << 6)) + lane);
            __half2 v6 = __ldg((const __half2*)(g_h + ((size_t)j6 << 6)) + lane);
            __half2 v7 = __ldg((const __half2*)(g_h + ((size_t)j7 << 6)) + lane);
            float2 f0 = __half22float2(v0), f1 = __half22float2(v1);
            float2 f2 = __half22float2(v2), f3 = __half22float2(v3);
            float2 f4 = __half22float2(v4), f5 = __half22float2(v5);
            float2 f6 = __half22float2(v6), f7 = __half22float2(v7);
            a0.x += f0.x; a0.y += f0.y;  a1.x += f1.x; a1.y += f1.y;
            a2.x += f2.x; a2.y += f2.y;  a3.x += f3.x; a3.y += f3.y;
            a0.x += f4.x; a0.y += f4.y;  a1.x += f5.x; a1.y += f5.y;
            a2.x += f6.x; a2.y += f6.y;  a3.x += f7.x; a3.y += f7.y;
        }
        float px = (a0.x + a1.x) + (a2.x + a3.x);
        float py = (a0.y + a1.y) + (a2.y + a3.y);
        *(__half2*)&Ps_h[pt * 72 + (lane << 1)] = __floats2half2_rn(px, py);
    }
    __syncthreads();

    // ---- fp16 HMMA GEMM: D[pt 64][o 128] = P @ W^T.
    // 8 warps: mi = warp>>1 (pt tile of 16), nh = warp&1 (o half of 64).
    int mi = warp >> 1, nh = warp & 1;
    int lane7 = lane & 7, seg = lane >> 3;
    uint32_t ps_u = (uint32_t)__cvta_generic_to_shared(Ps_h);
    uint32_t ws_u = (uint32_t)__cvta_generic_to_shared(Ws_h);
    // A x4: lanes 0-7: m0-7@k0 | 8-15: m8-15@k0 | 16-23: m0-7@k8 | 24-31: m8-15@k8
    uint32_t a_base = ps_u + (((mi << 4) + ((seg & 1) << 3) + lane7) * 72 + ((seg >> 1) << 3)) * 2;
    // B x4 (n16 pair): 0-7: n0-7@k0 | 8-15: n0-7@k8 | 16-23: n8-15@k0 | 24-31: n8-15@k8
    uint32_t b_base = ws_u + (((nh << 6) + ((seg >> 1) << 3) + lane7) * 72 + ((seg & 1) << 3)) * 2;

    float c[4][8];
#pragma unroll
    for (int g = 0; g < 4; g++)
#pragma unroll
        for (int i = 0; i < 8; i++) c[g][i] = 0.f;

#pragma unroll
    for (int ks = 0; ks < 4; ks++) {          // K=64 in steps of 16: +32B per step
        uint32_t A0, A1, A2, A3;
        LDMX4(A0, A1, A2, A3, a_base + ks * 32);
#pragma unroll
        for (int g = 0; g < 4; g++) {         // o pair stride 16 rows = 16*72*2 = 2304B
            uint32_t B0, B1, B2, B3;
            LDMX4(B0, B1, B2, B3, b_base + g * 2304 + ks * 32);
            MMA16816(c[g][0], c[g][1], c[g][2], c[g][3], A0, A1, A2, A3, B0, B1);
            MMA16816(c[g][4], c[g][5], c[g][6], c[g][7], A0, A1, A2, A3, B2, B3);
        }
    }
    __syncthreads();   // all Ps_h/Ws_h reads done -> Ss may alias

    // epilogue: fragment (row lane>>2 (+8), col 2*(lane&3) (+1)) -> Ss[o][pt] + bias
    int row_lo = (mi << 4) + (lane >> 2);
    int col2   = (lane & 3) << 1;
#pragma unroll
    for (int g = 0; g < 4; g++) {
#pragma unroll
        for (int hh = 0; hh < 2; hh++) {
            int o0 = (nh << 6) + (g << 4) + (hh << 3) + col2;
            float b0v = __ldg(&bc[o0]);
            float b1v = __ldg(&bc[o0 + 1]);
            const float* cf = &c[g][hh << 2];
            Ss[o0 * 66 + row_lo]           = cf[0] + b0v;
            Ss[(o0 + 1) * 66 + row_lo]     = cf[1] + b1v;
            Ss[o0 * 66 + row_lo + 8]       = cf[2] + b0v;
            Ss[(o0 + 1) * 66 + row_lo + 8] = cf[3] + b1v;
        }
    }
    __syncthreads();

    // per-block BN partials (threads 0..127: one output channel each)
    if (t < OUTC) {
        float s = 0.f, s2 = 0.f;
#pragma unroll 8
        for (int pt = 0; pt < 64; pt++) {
            float v = Ss[t * 66 + pt];
            s += v;
            s2 = fmaf(v, v, s2);
        }
        atomicAdd(&g_sum[t], s);
        atomicAdd(&g_sqs[t], s2);
    }

    // coalesced fp16 store of the unnormalized tile: g_tmp[b, o, n0+i] (half2 packed)
    size_t obase = (size_t)b * OUTC * NN + n0;    // even
#pragma unroll
    for (int r = 0; r < 16; r++) {
        int e  = r * 256 + t;       // 4096 half2 elements: o = e>>5, i2 = e&31
        int o  = e >> 5, i2 = e & 31;
        __half2 hv = __floats2half2_rn(Ss[o * 66 + 2 * i2], Ss[o * 66 + 2 * i2 + 1]);
        *((__half2*)(g_tmp + obase + (size_t)o * NN) + i2) = hv;
    }
}

// ---------------- K5: finalize BN stats per-thread + normalize fp16 tmp -> fp32 out ----------
__global__ void k5_norm(const float* __restrict__ gamma, const float* __restrict__ beta,
                        float* __restrict__ out) {
    int gi = blockIdx.x * blockDim.x + threadIdx.x;   // 0 .. 2M-1 float4s
    int o  = (gi >> 12) & (OUTC - 1);                 // 4096 float4 per (b,o) row
    const float invn = 1.0f / (float)BN;
    float mean = __ldg(&g_sum[o]) * invn;
    float var  = __ldg(&g_sqs[o]) * invn - mean * mean;
    float inv  = rsqrtf(var + 1e-5f);
    float a    = __ldg(&gamma[o]) * inv;
    float s    = __ldg(&beta[o]) - mean * a;
    const __half2* tp = (const __half2*)g_tmp + 2 * gi;
    float2 lo = __half22float2(__ldg(tp + 0));
    float2 hi = __half22float2(__ldg(tp + 1));
    float4 v;
    v.x = fmaf(lo.x, a, s);
    v.y = fmaf(lo.y, a, s);
    v.z = fmaf(hi.x, a, s);
    v.w = fmaf(hi.y, a, s);
    ((float4*)out)[gi] = v;
}

// ---------------- launch ----------------
extern "C" void kernel_launch(void* const* d_in, const int* in_sizes, int n_in,
                              void* d_out, int out_size) {
    const float* feat  = (const float*)d_in[0];
    const int*   nidx  = (const int*)d_in[1];
    // d_in[2] = permatrix (unused by forward)
    const float* Wm    = (const float*)d_in[3];
    const float* Wc    = (const float*)d_in[4];
    const float* bc    = (const float*)d_in[5];
    const float* gamma = (const float*)d_in[6];
    const float* beta  = (const float*)d_in[7];
    float*       out   = (float*)d_out;

    const int smem_k23 = 128 * 66 * (int)sizeof(float);  // 33792 B (Ss, aliases Ps_h+Ws_h)
    k1_mlp_h<<<BN / 64, 256>>>(feat, Wm);
    k23_pool_conv<<<BN / 64, 256, smem_k23>>>(nidx, Wc, bc);
    k5_norm<<<(BB * OUTC * NN / 4) / 256, 256>>>(gamma, beta, out);
}

// round 15
// speedup vs baseline: 1.7672x; 1.0922x over previous
#include <cuda_runtime.h>
#include <cuda_fp16.h>
#include <cuda_bf16.h>
#include <cstdint>

// Problem constants
#define BB   4
#define NN   16384
#define CC   64
#define KK   16
#define OUTC 128
#define BN   65536   // BB*NN

typedef unsigned long long ull;

#define LDMX4(r0, r1, r2, r3, addr) \
    asm volatile("ldmatrix.sync.aligned.m8n8.x4.shared.b16 {%0,%1,%2,%3}, [%4];" \
        : "=r"(r0), "=r"(r1), "=r"(r2), "=r"(r3) : "r"(addr))

#define MMA16816(c0, c1, c2, c3, a0, a1, a2, a3, b0, b1) \
    asm volatile("mma.sync.aligned.m16n8k16.row.col.f32.f16.f16.f32 " \
        "{%0,%1,%2,%3}, {%4,%5,%6,%7}, {%8,%9}, {%0,%1,%2,%3};" \
        : "+f"(c0), "+f"(c1), "+f"(c2), "+f"(c3) \
        : "r"(a0), "r"(a1), "r"(a2), "r"(a3), "r"(b0), "r"(b1))

// ---------------- scratch (device globals; no allocation) ----------------
__device__ __half g_h[(size_t)BN * CC];              // h[j] (fp16, 8MB)
__device__ __half g_tmp[(size_t)BB * OUTC * NN];     // unnormalized out (fp16, 16.8MB)
__device__ float g_sum[OUTC];
__device__ float g_sqs[OUTC];

// ---------------- K1: split-fp16 HMMA GEMM(Wmlp) + softmax + ⊙flat -> g_h (fp16)
// Scores computed as Ah*Wh + Ah*Wl + Al*Wh (hi/lo fp16 split, fp32 accum) — accurate
// to ~2^-21, numerically equivalent to the fp32 path. grid 1024 (64-pt tiles) x 128 thr.
__global__ void __launch_bounds__(128) k1_mlp_h(const float* __restrict__ feat,
                                               const float* __restrict__ Wm) {
    __shared__ __align__(16) __half Ah[64 * 72];
    __shared__ __align__(16) __half Al[64 * 72];
    __shared__ __align__(16) __half Wh[64 * 72];
    __shared__ __align__(16) __half Wl[64 * 72];
    int blk = blockIdx.x;
    int b   = blk >> 8;            // 256 tiles per batch (N/64)
    int n0  = (blk & 255) << 6;
    int t   = threadIdx.x;

    // fused k0: zero BN accumulators (ordered before k23's atomics by stream order)
    if (blk == 0 && t < OUTC) { g_sum[t] = 0.f; g_sqs[t] = 0.f; }

    // load W_mlp[d][c] -> hi/lo fp16 (c contiguous)
    const float2* wm2 = (const float2*)Wm;
#pragma unroll
    for (int r = 0; r < 16; r++) {
        int e2 = r * 128 + t;            // 2048 float2
        int d = e2 >> 5, c2 = e2 & 31;
        float2 wv = __ldg(wm2 + e2);
        __half hx = __float2half_rn(wv.x), hy = __float2half_rn(wv.y);
        *(__half2*)&Wh[d * 72 + (c2 << 1)] = __halves2half2(hx, hy);
        *(__half2*)&Wl[d * 72 + (c2 << 1)] =
            __floats2half2_rn(wv.x - __half2float(hx), wv.y - __half2float(hy));
    }

    // load feature[b, c, n0+i] (coalesced over i) -> transposed hi/lo Ah/Al[i][c]
    const float* fb = feat + (size_t)b * CC * NN;
#pragma unroll
    for (int r = 0; r < 32; r++) {
        int e = r * 128 + t;             // 4096 elems
        int c = e >> 6, i = e & 63;
        float f = fb[c * NN + n0 + i];
        __half h = __float2half_rn(f);
        Ah[i * 72 + c] = h;
        Al[i * 72 + c] = __float2half_rn(f - __half2float(h));
    }
    __syncthreads();

    // HMMA: warp w -> pt rows 16w..16w+15, full d 0..63.
    int warp = t >> 5, lane = t & 31;
    int lane7 = lane & 7, seg = lane >> 3;
    uint32_t ah_u = (uint32_t)__cvta_generic_to_shared(Ah);
    uint32_t al_u = (uint32_t)__cvta_generic_to_shared(Al);
    uint32_t wh_u = (uint32_t)__cvta_generic_to_shared(Wh);
    uint32_t wl_u = (uint32_t)__cvta_generic_to_shared(Wl);
    uint32_t a_off = (uint32_t)((((warp << 4) + ((seg & 1) << 3) + lane7) * 72 + ((seg >> 1) << 3)) * 2);
    uint32_t b_off = (uint32_t)(((((seg >> 1) << 3) + lane7) * 72 + ((seg & 1) << 3)) * 2);

    float cf[4][8];
#pragma unroll
    for (int g = 0; g < 4; g++)
#pragma unroll
        for (int i = 0; i < 8; i++) cf[g][i] = 0.f;

#pragma unroll
    for (int ks = 0; ks < 4; ks++) {     // K=64, steps of 16 (+32B)
        uint32_t H0, H1, H2, H3, L0, L1, L2, L3;
        LDMX4(H0, H1, H2, H3, ah_u + a_off + ks * 32);
        LDMX4(L0, L1, L2, L3, al_u + a_off + ks * 32);
#pragma unroll
        for (int g = 0; g < 4; g++) {    // d-tile stride 16 rows = 2304B
            uint32_t B0, B1, B2, B3, C0, C1, C2, C3;
            LDMX4(B0, B1, B2, B3, wh_u + b_off + g * 2304 + ks * 32);
            LDMX4(C0, C1, C2, C3, wl_u + b_off + g * 2304 + ks * 32);
            // Ah*Wh
            MMA16816(cf[g][0], cf[g][1], cf[g][2], cf[g][3], H0, H1, H2, H3, B0, B1);
            MMA16816(cf[g][4], cf[g][5], cf[g][6], cf[g][7], H0, H1, H2, H3, B2, B3);
            // Ah*Wl
            MMA16816(cf[g][0], cf[g][1], cf[g][2], cf[g][3], H0, H1, H2, H3, C0, C1);
            MMA16816(cf[g][4], cf[g][5], cf[g][6], cf[g][7], H0, H1, H2, H3, C2, C3);
            // Al*Wh
            MMA16816(cf[g][0], cf[g][1], cf[g][2], cf[g][3], L0, L1, L2, L3, B0, B1);
            MMA16816(cf[g][4], cf[g][5], cf[g][6], cf[g][7], L0, L1, L2, L3, B2, B3);
        }
    }

    // softmax epilogue on fragments (scores ~N(0,1): no max-subtraction needed).
    // frag map: cf[g][0,1]=row_lo d=16g+2l3{+1}; [2,3]=row_hi; [4..7]= same at d+8.
#pragma unroll
    for (int g = 0; g < 4; g++)
#pragma unroll
        for (int i = 0; i < 8; i++) cf[g][i] = __expf(cf[g][i]);

    float rs_lo = 0.f, rs_hi = 0.f;
#pragma unroll
    for (int g = 0; g < 4; g++) {
        rs_lo += (cf[g][0] + cf[g][1]) + (cf[g][4] + cf[g][5]);
        rs_hi += (cf[g][2] + cf[g][3]) + (cf[g][6] + cf[g][7]);
    }
    rs_lo += __shfl_xor_sync(0xffffffffu, rs_lo, 1);
    rs_lo += __shfl_xor_sync(0xffffffffu, rs_lo, 2);
    rs_hi += __shfl_xor_sync(0xffffffffu, rs_hi, 1);
    rs_hi += __shfl_xor_sync(0xffffffffu, rs_hi, 2);
    float ri_lo = __fdividef(1.0f, rs_lo);
    float ri_hi = __fdividef(1.0f, rs_hi);

    int row_lo = (warp << 4) + (lane >> 2);
    int row_hi = row_lo + 8;
    __half* hbase = g_h + (((size_t)b * NN + n0) << 6);
#pragma unroll
    for (int g = 0; g < 4; g++) {
#pragma unroll
        for (int hh = 0; hh < 2; hh++) {
            int col = (g << 4) + (hh << 3) + ((lane & 3) << 1);
            int ci  = hh << 2;
            // reconstruct flat = hi + lo (exact to 2^-22)
            __half2 a_lo = *(__half2*)&Ah[row_lo * 72 + col];
            __half2 l_lo = *(__half2*)&Al[row_lo * 72 + col];
            __half2 a_hi = *(__half2*)&Ah[row_hi * 72 + col];
            __half2 l_hi = *(__half2*)&Al[row_hi * 72 + col];
            float f0 = __half2float(a_lo.x) + __half2float(l_lo.x);
            float f1 = __half2float(a_lo.y) + __half2float(l_lo.y);
            float f2 = __half2float(a_hi.x) + __half2float(l_hi.x);
            float f3 = __half2float(a_hi.y) + __half2float(l_hi.y);
            *(__half2*)&hbase[row_lo * 64 + col] =
                __floats2half2_rn(cf[g][ci] * ri_lo * f0, cf[g][ci + 1] * ri_lo * f1);
            *(__half2*)&hbase[row_hi * 64 + col] =
                __floats2half2_rn(cf[g][ci + 2] * ri_hi * f2, cf[g][ci + 3] * ri_hi * f3);
        }
    }
}

// ---------------- K23: fused gather-pool + fp16 HMMA GEMM(Wconv)+bias + BN partials
//                  + fp16 store of unnormalized out.  (identical to the 51.9us version)
#define PS_BYTES (64 * 72 * 2)
__global__ void __launch_bounds__(256) k23_pool_conv(const int* __restrict__ nidx,
                              const float* __restrict__ Wc, const float* __restrict__ bc) {
    extern __shared__ __align__(16) char shb[];
    __half* Ps_h = (__half*)shb;                 // [pt][c] pitch 72 halves
    __half* Ws_h = (__half*)(shb + PS_BYTES);    // [o][c] pitch 72 halves
    float*  Ss   = (float*)shb;                  // [o][pt] pitch 66, alias after GEMM

    int blk = blockIdx.x;
    int b   = blk >> 8;
    int n0  = (blk & 255) << 6;
    int t   = threadIdx.x;
    int warp = t >> 5, lane = t & 31;

    // load + convert W_conv[o][c] -> fp16 Ws_h (no sync needed before gather writes Ps_h)
    const float2* wc2 = (const float2*)Wc;
#pragma unroll
    for (int r = 0; r < 16; r++) {
        int e2 = r * 256 + t;            // 4096 float2
        int o = e2 >> 5, c2 = e2 & 31;
        float2 wv = __ldg(wc2 + e2);
        *(__half2*)&Ws_h[o * 72 + (c2 << 1)] = __floats2half2_rn(wv.x, wv.y);
    }

    // gather-pool: warp w handles points 8w..8w+7; pooled_p = sum_k h[idx[p,k]]
    size_t prow0 = ((size_t)b * NN + n0);
    int4 myi = __ldg((const int4*)(nidx + ((prow0 + warp * 8) << 4)) + lane);
#pragma unroll 1
    for (int pi = 0; pi < 8; pi++) {
        int pt = warp * 8 + pi;
        float2 a0 = {0.f, 0.f}, a1 = {0.f, 0.f};
        float2 a2 = {0.f, 0.f}, a3 = {0.f, 0.f};
#pragma unroll
        for (int k = 0; k < KK; k += 8) {
            int f = pi * 16 + k;
            int j0 = __shfl_sync(0xffffffffu, myi.x, (f + 0) >> 2);
            int j1 = __shfl_sync(0xffffffffu, myi.y, (f + 1) >> 2);
            int j2 = __shfl_sync(0xffffffffu, myi.z, (f + 2) >> 2);
            int j3 = __shfl_sync(0xffffffffu, myi.w, (f + 3) >> 2);
            int j4 = __shfl_sync(0xffffffffu, myi.x, (f + 4) >> 2);
            int j5 = __shfl_sync(0xffffffffu, myi.y, (f + 5) >> 2);
            int j6 = __shfl_sync(0xffffffffu, myi.z, (f + 6) >> 2);
            int j7 = __shfl_sync(0xffffffffu, myi.w, (f + 7) >> 2);
            __half2 v0 = __ldg((const __half2*)(g_h + ((size_t)j0 << 6)) + lane);
            __half2 v1 = __ldg((const __half2*)(g_h + ((size_t)j1 << 6)) + lane);
            __half2 v2 = __ldg((const __half2*)(g_h + ((size_t)j2 << 6)) + lane);
            __half2 v3 = __ldg((const __half2*)(g_h + ((size_t)j3 << 6)) + lane);
            __half2 v4 = __ldg((const __half2*)(g_h + ((size_t)j4 << 6)) + lane);
            __half2 v5 = __ldg((const __half2*)(g_h + ((size_t)j5 << 6)) + lane);
            __half2 v6 = __ldg((const __half2*)(g_h + ((size_t)j6 << 6)) + lane);
            __half2 v7 = __ldg((const __half2*)(g_h + ((size_t)j7 << 6)) + lane);
            float2 f0 = __half22float2(v0), f1 = __half22float2(v1);
            float2 f2 = __half22float2(v2), f3 = __half22float2(v3);
            float2 f4 = __half22float2(v4), f5 = __half22float2(v5);
            float2 f6 = __half22float2(v6), f7 = __half22float2(v7);
            a0.x += f0.x; a0.y += f0.y;  a1.x += f1.x; a1.y += f1.y;
            a2.x += f2.x; a2.y += f2.y;  a3.x += f3.x; a3.y += f3.y;
            a0.x += f4.x; a0.y += f4.y;  a1.x += f5.x; a1.y += f5.y;
            a2.x += f6.x; a2.y += f6.y;  a3.x += f7.x; a3.y += f7.y;
        }
        float px = (a0.x + a1.x) + (a2.x + a3.x);
        float py = (a0.y + a1.y) + (a2.y + a3.y);
        *(__half2*)&Ps_h[pt * 72 + (lane << 1)] = __floats2half2_rn(px, py);
    }
    __syncthreads();

    // ---- fp16 HMMA GEMM: D[pt 64][o 128] = P @ W^T.
    int mi = warp >> 1, nh = warp & 1;
    int lane7 = lane & 7, seg = lane >> 3;
    uint32_t ps_u = (uint32_t)__cvta_generic_to_shared(Ps_h);
    uint32_t ws_u = (uint32_t)__cvta_generic_to_shared(Ws_h);
    uint32_t a_base = ps_u + (((mi << 4) + ((seg & 1) << 3) + lane7) * 72 + ((seg >> 1) << 3)) * 2;
    uint32_t b_base = ws_u + (((nh << 6) + ((seg >> 1) << 3) + lane7) * 72 + ((seg & 1) << 3)) * 2;

    float c[4][8];
#pragma unroll
    for (int g = 0; g < 4; g++)
#pragma unroll
        for (int i = 0; i < 8; i++) c[g][i] = 0.f;

#pragma unroll
    for (int ks = 0; ks < 4; ks++) {
        uint32_t A0, A1, A2, A3;
        LDMX4(A0, A1, A2, A3, a_base + ks * 32);
#pragma unroll
        for (int g = 0; g < 4; g++) {
            uint32_t B0, B1, B2, B3;
            LDMX4(B0, B1, B2, B3, b_base + g * 2304 + ks * 32);
            MMA16816(c[g][0], c[g][1], c[g][2], c[g][3], A0, A1, A2, A3, B0, B1);
            MMA16816(c[g][4], c[g][5], c[g][6], c[g][7], A0, A1, A2, A3, B2, B3);
        }
    }
    __syncthreads();   // all Ps_h/Ws_h reads done -> Ss may alias

    int row_lo = (mi << 4) + (lane >> 2);
    int col2   = (lane & 3) << 1;
#pragma unroll
    for (int g = 0; g < 4; g++) {
#pragma unroll
        for (int hh = 0; hh < 2; hh++) {
            int o0 = (nh << 6) + (g << 4) + (hh << 3) + col2;
            float b0v = __ldg(&bc[o0]);
            float b1v = __ldg(&bc[o0 + 1]);
            const float* cff = &c[g][hh << 2];
            Ss[o0 * 66 + row_lo]           = cff[0] + b0v;
            Ss[(o0 + 1) * 66 + row_lo]     = cff[1] + b1v;
            Ss[o0 * 66 + row_lo + 8]       = cff[2] + b0v;
            Ss[(o0 + 1) * 66 + row_lo + 8] = cff[3] + b1v;
        }
    }
    __syncthreads();

    // per-block BN partials (threads 0..127: one output channel each)
    if (t < OUTC) {
        float s = 0.f, s2 = 0.f;
#pragma unroll 8
        for (int pt = 0; pt < 64; pt++) {
            float v = Ss[t * 66 + pt];
            s += v;
            s2 = fmaf(v, v, s2);
        }
        atomicAdd(&g_sum[t], s);
        atomicAdd(&g_sqs[t], s2);
    }

    // coalesced fp16 store of the unnormalized tile: g_tmp[b, o, n0+i] (half2 packed)
    size_t obase = (size_t)b * OUTC * NN + n0;    // even
#pragma unroll
    for (int r = 0; r < 16; r++) {
        int e  = r * 256 + t;       // 4096 half2 elements: o = e>>5, i2 = e&31
        int o  = e >> 5, i2 = e & 31;
        __half2 hv = __floats2half2_rn(Ss[o * 66 + 2 * i2], Ss[o * 66 + 2 * i2 + 1]);
        *((__half2*)(g_tmp + obase + (size_t)o * NN) + i2) = hv;
    }
}

// ---------------- K5: finalize BN stats per-thread + normalize fp16 tmp -> fp32 out ----------
__global__ void k5_norm(const float* __restrict__ gamma, const float* __restrict__ beta,
                        float* __restrict__ out) {
    int gi = blockIdx.x * blockDim.x + threadIdx.x;   // 0 .. 2M-1 float4s
    int o  = (gi >> 12) & (OUTC - 1);                 // 4096 float4 per (b,o) row
    const float invn = 1.0f / (float)BN;
    float mean = __ldg(&g_sum[o]) * invn;
    float var  = __ldg(&g_sqs[o]) * invn - mean * mean;
    float inv  = rsqrtf(var + 1e-5f);
    float a    = __ldg(&gamma[o]) * inv;
    float s    = __ldg(&beta[o]) - mean * a;
    const __half2* tp = (const __half2*)g_tmp + 2 * gi;
    float2 lo = __half22float2(__ldg(tp + 0));
    float2 hi = __half22float2(__ldg(tp + 1));
    float4 v;
    v.x = fmaf(lo.x, a, s);
    v.y = fmaf(lo.y, a, s);
    v.z = fmaf(hi.x, a, s);
    v.w = fmaf(hi.y, a, s);
    ((float4*)out)[gi] = v;
}

// ---------------- launch ----------------
extern "C" void kernel_launch(void* const* d_in, const int* in_sizes, int n_in,
                              void* d_out, int out_size) {
    const float* feat  = (const float*)d_in[0];
    const int*   nidx  = (const int*)d_in[1];
    // d_in[2] = permatrix (unused by forward)
    const float* Wm    = (const float*)d_in[3];
    const float* Wc    = (const float*)d_in[4];
    const float* bc    = (const float*)d_in[5];
    const float* gamma = (const float*)d_in[6];
    const float* beta  = (const float*)d_in[7];
    float*       out   = (float*)d_out;

    const int smem_k23 = 128 * 66 * (int)sizeof(float);  // 33792 B (Ss, aliases Ps_h+Ws_h)
    k1_mlp_h<<<BN / 64, 128>>>(feat, Wm);
    k23_pool_conv<<<BN / 64, 256, smem_k23>>>(nidx, Wc, bc);
    k5_norm<<<(BB * OUTC * NN / 4) / 256, 256>>>(gamma, beta, out);
}